// round 8
// baseline (speedup 1.0000x reference)
#include <cuda_runtime.h>
#include <cuda_fp16.h>
#include <cuda_bf16.h>
#include <mma.h>
#include <math.h>
#include <stdint.h>

using namespace nvcuda;

#define N_NODES 100000
#define N_PAD   (N_NODES + 64)
#define N_EDGES 3200000
#define N_TOT   (N_EDGES + N_NODES)
#define F_IN    512
#define F_MID   256
#define F_OUT   64
#define K_STEPS 10

// ---------------- scratch ----------------
__device__ __nv_bfloat16 g_t[(size_t)N_PAD * F_MID]; // relu(x@W1+b1), bf16
__device__ __half2 g_hh[(size_t)N_PAD * 32];         // h fp16 (unscaled)
__device__ __half2 g_y0[(size_t)N_PAD * 32];         // y = dinv*z ping
__device__ __half2 g_y1[(size_t)N_PAD * 32];         // pong
__device__ int     g_cnt[N_NODES];
__device__ int     g_off[N_NODES];
__device__ int     g_incl[N_NODES];
__device__ int     g_colptr[N_NODES + 1];
__device__ int     g_aux[128];
__device__ int     g_auxex[128];
__device__ float   g_dinv[N_NODES];
__device__ int     g_erow[N_TOT];

// ---------------- helpers ----------------
__device__ __forceinline__ uint4 pack8_bf16(float4 v0, float4 v1) {
    __nv_bfloat162 p0 = __floats2bfloat162_rn(v0.x, v0.y);
    __nv_bfloat162 p1 = __floats2bfloat162_rn(v0.z, v0.w);
    __nv_bfloat162 p2 = __floats2bfloat162_rn(v1.x, v1.y);
    __nv_bfloat162 p3 = __floats2bfloat162_rn(v1.z, v1.w);
    uint4 u;
    u.x = *(unsigned*)&p0; u.y = *(unsigned*)&p1;
    u.z = *(unsigned*)&p2; u.w = *(unsigned*)&p3;
    return u;
}

// ---------------- CSR build ----------------
__global__ void k_init() {
    int i = blockIdx.x * blockDim.x + threadIdx.x;
    if (i < N_NODES) { g_cnt[i] = 1; g_off[i] = 0; }
}
__global__ void k_count(const int* __restrict__ col) {
    int e = blockIdx.x * blockDim.x + threadIdx.x;
    if (e < N_EDGES) atomicAdd(&g_cnt[col[e]], 1);
}
__global__ void k_scan1() {   // block inclusive scan + dinv
    __shared__ int s[1024];
    int i = blockIdx.x * 1024 + threadIdx.x;
    int v = (i < N_NODES) ? g_cnt[i] : 0;
    if (i < N_NODES) g_dinv[i] = rsqrtf((float)v);
    s[threadIdx.x] = v;
    __syncthreads();
    for (int d = 1; d < 1024; d <<= 1) {
        int t = (threadIdx.x >= d) ? s[threadIdx.x - d] : 0;
        __syncthreads();
        s[threadIdx.x] += t;
        __syncthreads();
    }
    if (i < N_NODES) g_incl[i] = s[threadIdx.x];
    if (threadIdx.x == 1023) g_aux[blockIdx.x] = s[1023];
}
__global__ void k_scanaux(int nb) {      // 128-wide exclusive scan
    __shared__ int s[128];
    int v = (threadIdx.x < nb) ? g_aux[threadIdx.x] : 0;
    s[threadIdx.x] = v;
    __syncthreads();
    for (int d = 1; d < 128; d <<= 1) {
        int t = (threadIdx.x >= d) ? s[threadIdx.x - d] : 0;
        __syncthreads();
        s[threadIdx.x] += t;
        __syncthreads();
    }
    if (threadIdx.x < nb) g_auxex[threadIdx.x] = s[threadIdx.x] - v;
}
__global__ void k_finalize() {
    int i = blockIdx.x * blockDim.x + threadIdx.x;
    if (i < N_NODES) {
        g_colptr[i + 1] = g_incl[i] + g_auxex[i >> 10];
        if (i == 0) g_colptr[0] = 0;
    }
}
__global__ void k_fill(const int* __restrict__ rowp, const int* __restrict__ colp) {
    int i = blockIdx.x * blockDim.x + threadIdx.x;
    if (i < N_TOT) {
        int r, c;
        if (i < N_EDGES) { r = rowp[i]; c = colp[i]; }
        else             { r = c = i - N_EDGES; }
        int idx = g_colptr[c] + atomicAdd(&g_off[c], 1);
        g_erow[idx] = r;
    }
}

// ---------------- GEMM1: g_t = relu(x @ W1 + b1) -> bf16 ----------------
// BM=64, BN=256, BK=32, 256 thr, 2x4 warps, 32x64 warp tiles.
// 2-stage register-prefetch double buffer; epilogue fuses b1+relu, stores bf16.
#define G1_AS_LD 40
#define G1_BS_LD 264
#define G1_AS_BYTES (2 * 64 * G1_AS_LD * 2)          // 10240
#define G1_BS_BYTES (2 * 32 * G1_BS_LD * 2)          // 33792
#define G1_SMEM (G1_AS_BYTES + G1_BS_BYTES)          // 44032 (Cs 64x132 fp32 = 33792 aliases base)

__global__ __launch_bounds__(256) void k_gemm1(const float* __restrict__ A,
                                               const float* __restrict__ W1,
                                               const float* __restrict__ b1) {
    extern __shared__ char smraw[];
    __nv_bfloat16* As = (__nv_bfloat16*)smraw;                      // [2][64][40]
    __nv_bfloat16* Bs = (__nv_bfloat16*)(smraw + G1_AS_BYTES);      // [2][32][264]
    float* Cs = (float*)smraw;                                      // [64][132] (aliased)

    const int tid = threadIdx.x;
    const int warp = tid >> 5;
    const int wr = warp >> 2, wc = warp & 3;
    const int m0 = blockIdx.x * 64;

    wmma::fragment<wmma::accumulator, 16, 16, 16, float> c[2][4];
    #pragma unroll
    for (int i = 0; i < 2; i++)
        #pragma unroll
        for (int j = 0; j < 4; j++) wmma::fill_fragment(c[i][j], 0.f);

    const int ar = tid >> 2, ac8 = (tid & 3) << 3;
    const float* Arow = A + (size_t)min(m0 + ar, N_NODES - 1) * F_IN;

    float4 a0R, a1R, bR[4][2];

    // prologue: load + store tile 0
    a0R = *(const float4*)&Arow[ac8];
    a1R = *(const float4*)&Arow[ac8 + 4];
    #pragma unroll
    for (int l = 0; l < 4; l++) {
        int idx = tid + l * 256;
        int br = idx >> 5, bc8 = (idx & 31) << 3;
        bR[l][0] = *(const float4*)&W1[(size_t)br * F_MID + bc8];
        bR[l][1] = *(const float4*)&W1[(size_t)br * F_MID + bc8 + 4];
    }
    *(uint4*)&As[ar * G1_AS_LD + ac8] = pack8_bf16(a0R, a1R);
    #pragma unroll
    for (int l = 0; l < 4; l++) {
        int idx = tid + l * 256;
        int br = idx >> 5, bc8 = (idx & 31) << 3;
        *(uint4*)&Bs[br * G1_BS_LD + bc8] = pack8_bf16(bR[l][0], bR[l][1]);
    }
    __syncthreads();

    constexpr int NKT = F_IN / 32;   // 16
    for (int kt = 0; kt < NKT; kt++) {
        const int buf = kt & 1;
        if (kt + 1 < NKT) {          // issue next tile's loads early
            const int k0 = (kt + 1) * 32;
            a0R = *(const float4*)&Arow[k0 + ac8];
            a1R = *(const float4*)&Arow[k0 + ac8 + 4];
            #pragma unroll
            for (int l = 0; l < 4; l++) {
                int idx = tid + l * 256;
                int br = idx >> 5, bc8 = (idx & 31) << 3;
                bR[l][0] = *(const float4*)&W1[(size_t)(k0 + br) * F_MID + bc8];
                bR[l][1] = *(const float4*)&W1[(size_t)(k0 + br) * F_MID + bc8 + 4];
            }
        }
        const __nv_bfloat16* Asb = As + buf * (64 * G1_AS_LD);
        const __nv_bfloat16* Bsb = Bs + buf * (32 * G1_BS_LD);
        #pragma unroll
        for (int kk = 0; kk < 32; kk += 16) {
            wmma::fragment<wmma::matrix_a, 16, 16, 16, __nv_bfloat16, wmma::row_major> a0, a1;
            wmma::load_matrix_sync(a0, &Asb[(wr * 32) * G1_AS_LD + kk],      G1_AS_LD);
            wmma::load_matrix_sync(a1, &Asb[(wr * 32 + 16) * G1_AS_LD + kk], G1_AS_LD);
            #pragma unroll
            for (int j = 0; j < 4; j++) {
                wmma::fragment<wmma::matrix_b, 16, 16, 16, __nv_bfloat16, wmma::row_major> b;
                wmma::load_matrix_sync(b, &Bsb[kk * G1_BS_LD + wc * 64 + j * 16], G1_BS_LD);
                wmma::mma_sync(c[0][j], a0, b, c[0][j]);
                wmma::mma_sync(c[1][j], a1, b, c[1][j]);
            }
        }
        if (kt + 1 < NKT) {          // store prefetched tile into other buffer
            __nv_bfloat16* Asn = (__nv_bfloat16*)As + (buf ^ 1) * (64 * G1_AS_LD);
            __nv_bfloat16* Bsn = (__nv_bfloat16*)Bs + (buf ^ 1) * (32 * G1_BS_LD);
            *(uint4*)&Asn[ar * G1_AS_LD + ac8] = pack8_bf16(a0R, a1R);
            #pragma unroll
            for (int l = 0; l < 4; l++) {
                int idx = tid + l * 256;
                int br = idx >> 5, bc8 = (idx & 31) << 3;
                *(uint4*)&Bsn[br * G1_BS_LD + bc8] = pack8_bf16(bR[l][0], bR[l][1]);
            }
        }
        __syncthreads();
    }

    // epilogue: two 128-col halves through Cs (aliases pipeline smem)
    #pragma unroll
    for (int half = 0; half < 2; half++) {
        if ((wc >> 1) == half) {
            int wcl = wc & 1;
            #pragma unroll
            for (int i = 0; i < 2; i++)
                #pragma unroll
                for (int j = 0; j < 4; j++)
                    wmma::store_matrix_sync(&Cs[(wr * 32 + i * 16) * 132 + wcl * 64 + j * 16],
                                            c[i][j], 132, wmma::mem_row_major);
        }
        __syncthreads();
        #pragma unroll
        for (int l = 0; l < 4; l++) {
            int idx = tid + l * 256;            // 1024 chunks of 8 floats (64 x 128)
            int r = idx >> 4, c8 = (idx & 15) << 3;
            float4 v0 = *(float4*)&Cs[r * 132 + c8];
            float4 v1 = *(float4*)&Cs[r * 132 + c8 + 4];
            float4 u0 = *(const float4*)&b1[half * 128 + c8];
            float4 u1 = *(const float4*)&b1[half * 128 + c8 + 4];
            v0.x = fmaxf(v0.x + u0.x, 0.f); v0.y = fmaxf(v0.y + u0.y, 0.f);
            v0.z = fmaxf(v0.z + u0.z, 0.f); v0.w = fmaxf(v0.w + u0.w, 0.f);
            v1.x = fmaxf(v1.x + u1.x, 0.f); v1.y = fmaxf(v1.y + u1.y, 0.f);
            v1.z = fmaxf(v1.z + u1.z, 0.f); v1.w = fmaxf(v1.w + u1.w, 0.f);
            *(uint4*)&g_t[(size_t)(m0 + r) * F_MID + half * 128 + c8] = pack8_bf16(v0, v1);
        }
        __syncthreads();
    }
}

// ---------------- GEMM2: h = t @ W2 + b2 (t already relu'd bf16) ----------------
#define A2_LD 40
#define B2_LD 80
__global__ __launch_bounds__(128) void k_gemm2(const float* __restrict__ B,
                                               const float* __restrict__ b2) {
    __shared__ __nv_bfloat16 As[64][A2_LD];
    __shared__ __nv_bfloat16 Bs[32][B2_LD];
    __shared__ float Cs[64][68];
    const int tid = threadIdx.x;
    const int warp = tid >> 5;
    const int wr = warp >> 1, wc = warp & 1;
    const int m0 = blockIdx.x * 64;

    wmma::fragment<wmma::accumulator, 16, 16, 16, float> c[2][2];
    #pragma unroll
    for (int i = 0; i < 2; i++)
        #pragma unroll
        for (int j = 0; j < 2; j++) wmma::fill_fragment(c[i][j], 0.f);

    for (int k0 = 0; k0 < F_MID; k0 += 32) {
        #pragma unroll
        for (int l = 0; l < 2; l++) {   // A tile 64x32 bf16: pure copy
            int idx = tid + l * 128;
            int r = idx >> 2, c8 = (idx & 3) << 3;
            *(uint4*)&As[r][c8] =
                *(const uint4*)&g_t[(size_t)(m0 + r) * F_MID + k0 + c8];
        }
        #pragma unroll
        for (int l = 0; l < 2; l++) {   // B tile 32x64
            int idx = tid + l * 128;
            int br = idx >> 3, bc8 = (idx & 7) << 3;
            float4 v0 = *(const float4*)&B[(size_t)(k0 + br) * F_OUT + bc8];
            float4 v1 = *(const float4*)&B[(size_t)(k0 + br) * F_OUT + bc8 + 4];
            *(uint4*)&Bs[br][bc8] = pack8_bf16(v0, v1);
        }
        __syncthreads();
        #pragma unroll
        for (int kk = 0; kk < 32; kk += 16) {
            wmma::fragment<wmma::matrix_a, 16, 16, 16, __nv_bfloat16, wmma::row_major> a0, a1;
            wmma::fragment<wmma::matrix_b, 16, 16, 16, __nv_bfloat16, wmma::row_major> b0, b1f;
            wmma::load_matrix_sync(a0, &As[wr * 32][kk],      A2_LD);
            wmma::load_matrix_sync(a1, &As[wr * 32 + 16][kk], A2_LD);
            wmma::load_matrix_sync(b0, &Bs[kk][wc * 32],      B2_LD);
            wmma::load_matrix_sync(b1f, &Bs[kk][wc * 32 + 16], B2_LD);
            wmma::mma_sync(c[0][0], a0, b0,  c[0][0]);
            wmma::mma_sync(c[0][1], a0, b1f, c[0][1]);
            wmma::mma_sync(c[1][0], a1, b0,  c[1][0]);
            wmma::mma_sync(c[1][1], a1, b1f, c[1][1]);
        }
        __syncthreads();
    }
    #pragma unroll
    for (int i = 0; i < 2; i++)
        #pragma unroll
        for (int j = 0; j < 2; j++)
            wmma::store_matrix_sync(&Cs[wr * 32 + i * 16][wc * 32 + j * 16],
                                    c[i][j], 68, wmma::mem_row_major);
    __syncthreads();
    #pragma unroll
    for (int l = 0; l < 8; l++) {
        int idx = tid + l * 128;
        int r = idx >> 4, c4 = (idx & 15) << 2;
        float4 v = *(float4*)&Cs[r][c4];
        float4 bb = *(const float4*)&b2[c4];
        v.x += bb.x; v.y += bb.y; v.z += bb.z; v.w += bb.w;
        int row = m0 + r;
        float di = (row < N_NODES) ? g_dinv[row] : 0.f;
        size_t oh = (size_t)row * 32 + (c4 >> 1);
        g_hh[oh]     = __floats2half2_rn(v.x, v.y);
        g_hh[oh + 1] = __floats2half2_rn(v.z, v.w);
        g_y0[oh]     = __floats2half2_rn(di * v.x, di * v.y);
        g_y0[oh + 1] = __floats2half2_rn(di * v.z, di * v.w);
    }
}

// ---------------- APPNP propagation ----------------
__device__ __forceinline__ void acc8(float2& a0, float2& a1, float2& a2, float2& a3,
                                     const __half2* __restrict__ zin, int r, int k) {
    float4 v = *(const float4*)&zin[(size_t)r * 32 + k * 4];
    const __half2* hp = (const __half2*)&v;
    float2 t0 = __half22float2(hp[0]);
    float2 t1 = __half22float2(hp[1]);
    float2 t2 = __half22float2(hp[2]);
    float2 t3 = __half22float2(hp[3]);
    a0.x += t0.x; a0.y += t0.y;
    a1.x += t1.x; a1.y += t1.y;
    a2.x += t2.x; a2.y += t2.y;
    a3.x += t3.x; a3.y += t3.y;
}

__global__ void k_prop(float* __restrict__ outF, int it) {
    const __half2* __restrict__ zin = (it & 1) ? g_y1 : g_y0;
    __half2* __restrict__ zout = (it & 1) ? g_y0 : g_y1;
    const int warp = threadIdx.x >> 5, lane = threadIdx.x & 31;
    const int node = blockIdx.x * 8 + warp;
    if (node >= N_NODES) return;
    const int g = lane >> 3, k = lane & 7;
    const int s = g_colptr[node], e = g_colptr[node + 1];

    float2 a0 = {0.f, 0.f}, a1 = {0.f, 0.f}, a2 = {0.f, 0.f}, a3 = {0.f, 0.f};
    int i = s + g;
    while (i + 12 < e) {                 // four independent 512B gathers in flight
        int r0 = g_erow[i];
        int r1 = g_erow[i + 4];
        int r2 = g_erow[i + 8];
        int r3 = g_erow[i + 12];
        acc8(a0, a1, a2, a3, zin, r0, k);
        acc8(a0, a1, a2, a3, zin, r1, k);
        acc8(a0, a1, a2, a3, zin, r2, k);
        acc8(a0, a1, a2, a3, zin, r3, k);
        i += 16;
    }
    while (i < e) {
        acc8(a0, a1, a2, a3, zin, g_erow[i], k);
        i += 4;
    }
    #pragma unroll
    for (int d = 8; d <= 16; d <<= 1) {
        a0.x += __shfl_xor_sync(0xffffffffu, a0.x, d);
        a0.y += __shfl_xor_sync(0xffffffffu, a0.y, d);
        a1.x += __shfl_xor_sync(0xffffffffu, a1.x, d);
        a1.y += __shfl_xor_sync(0xffffffffu, a1.y, d);
        a2.x += __shfl_xor_sync(0xffffffffu, a2.x, d);
        a2.y += __shfl_xor_sync(0xffffffffu, a2.y, d);
        a3.x += __shfl_xor_sync(0xffffffffu, a3.x, d);
        a3.y += __shfl_xor_sync(0xffffffffu, a3.y, d);
    }
    const float dc = g_dinv[node];
    float4 hv = *(const float4*)&g_hh[(size_t)node * 32 + k * 4];
    const __half2* hp = (const __half2*)&hv;
    float2 h0 = __half22float2(hp[0]), h1 = __half22float2(hp[1]);
    float2 h2 = __half22float2(hp[2]), h3 = __half22float2(hp[3]);
    const float w = 0.9f * dc;
    float z0x = w * a0.x + 0.1f * h0.x, z0y = w * a0.y + 0.1f * h0.y;
    float z1x = w * a1.x + 0.1f * h1.x, z1y = w * a1.y + 0.1f * h1.y;
    float z2x = w * a2.x + 0.1f * h2.x, z2y = w * a2.y + 0.1f * h2.y;
    float z3x = w * a3.x + 0.1f * h3.x, z3y = w * a3.y + 0.1f * h3.y;

    if (it != K_STEPS - 1) {
        if (g == 0) {
            __half2 o0 = __floats2half2_rn(dc * z0x, dc * z0y);
            __half2 o1 = __floats2half2_rn(dc * z1x, dc * z1y);
            __half2 o2 = __floats2half2_rn(dc * z2x, dc * z2y);
            __half2 o3 = __floats2half2_rn(dc * z3x, dc * z3y);
            uint4 pk;
            pk.x = *(unsigned*)&o0; pk.y = *(unsigned*)&o1;
            pk.z = *(unsigned*)&o2; pk.w = *(unsigned*)&o3;
            *(uint4*)&zout[(size_t)node * 32 + k * 4] = pk;
        }
    } else {
        float m = fmaxf(fmaxf(fmaxf(z0x, z0y), fmaxf(z1x, z1y)),
                        fmaxf(fmaxf(z2x, z2y), fmaxf(z3x, z3y)));
        #pragma unroll
        for (int d = 1; d <= 4; d <<= 1) m = fmaxf(m, __shfl_xor_sync(0xffffffffu, m, d));
        float sm = __expf(z0x - m) + __expf(z0y - m) + __expf(z1x - m) + __expf(z1y - m)
                 + __expf(z2x - m) + __expf(z2y - m) + __expf(z3x - m) + __expf(z3y - m);
        #pragma unroll
        for (int d = 1; d <= 4; d <<= 1) sm += __shfl_xor_sync(0xffffffffu, sm, d);
        float l = m + __logf(sm);
        if (g == 0) {
            float4 o;
            o.x = z0x - l; o.y = z0y - l; o.z = z1x - l; o.w = z1y - l;
            *(float4*)&outF[(size_t)node * F_OUT + k * 8] = o;
            o.x = z2x - l; o.y = z2y - l; o.z = z3x - l; o.w = z3y - l;
            *(float4*)&outF[(size_t)node * F_OUT + k * 8 + 4] = o;
        }
    }
}

// ---------------- launch ----------------
extern "C" void kernel_launch(void* const* d_in, const int* in_sizes, int n_in,
                              void* d_out, int out_size) {
    const float* x  = (const float*)d_in[0];
    const int*   ei = (const int*)d_in[1];
    const float* W1 = (const float*)d_in[2];
    const float* b1 = (const float*)d_in[3];
    const float* W2 = (const float*)d_in[4];
    const float* b2 = (const float*)d_in[5];
    float* out = (float*)d_out;

    const int* rowp = ei;
    const int* colp = ei + N_EDGES;

    // CSR-by-destination build
    k_init<<<(N_NODES + 255) / 256, 256>>>();
    k_count<<<(N_EDGES + 255) / 256, 256>>>(colp);
    int nb = (N_NODES + 1023) / 1024;
    k_scan1<<<nb, 1024>>>();
    k_scanaux<<<1, 128>>>(nb);
    k_finalize<<<(N_NODES + 255) / 256, 256>>>();
    k_fill<<<(N_TOT + 255) / 256, 256>>>(rowp, colp);

    // MLP (bf16 tensor cores, fp32 accumulate)
    int mb = (N_NODES + 63) / 64;     // 1563
    k_gemm1<<<mb, 256, G1_SMEM>>>(x, W1, b1);
    k_gemm2<<<mb, 128>>>(W2, b2);

    // K propagation steps
    for (int it = 0; it < K_STEPS; ++it)
        k_prop<<<(N_NODES + 7) / 8, 256>>>(out, it);
}

// round 9
// speedup vs baseline: 1.1161x; 1.1161x over previous
#include <cuda_runtime.h>
#include <cuda_fp16.h>
#include <cuda_bf16.h>
#include <mma.h>
#include <math.h>
#include <stdint.h>

using namespace nvcuda;

#define N_NODES 100000
#define N_PAD   (N_NODES + 64)
#define N_EDGES 3200000
#define N_TOT   (N_EDGES + N_NODES)
#define F_IN    512
#define F_MID   256
#define F_OUT   64
#define K_STEPS 10

// ---------------- scratch ----------------
__device__ __nv_bfloat16 g_t[(size_t)N_PAD * F_MID]; // relu(x@W1+b1), bf16
__device__ __half2 g_hh[(size_t)N_PAD * 32];         // h fp16 (unscaled)
__device__ __half2 g_y0[(size_t)N_PAD * 32];         // y = dinv*z ping
__device__ __half2 g_y1[(size_t)N_PAD * 32];         // pong
__device__ int     g_cnt[N_NODES];
__device__ int     g_off[N_NODES];
__device__ int     g_incl[N_NODES];
__device__ int     g_colptr[N_NODES + 1];
__device__ int     g_aux[128];
__device__ int     g_auxex[128];
__device__ float   g_dinv[N_NODES];
__device__ int     g_erow[N_TOT];

// ---------------- helpers ----------------
__device__ __forceinline__ uint4 pack8_bf16(float4 v0, float4 v1) {
    __nv_bfloat162 p0 = __floats2bfloat162_rn(v0.x, v0.y);
    __nv_bfloat162 p1 = __floats2bfloat162_rn(v0.z, v0.w);
    __nv_bfloat162 p2 = __floats2bfloat162_rn(v1.x, v1.y);
    __nv_bfloat162 p3 = __floats2bfloat162_rn(v1.z, v1.w);
    uint4 u;
    u.x = *(unsigned*)&p0; u.y = *(unsigned*)&p1;
    u.z = *(unsigned*)&p2; u.w = *(unsigned*)&p3;
    return u;
}

// ---------------- CSR build ----------------
__global__ void k_init() {
    int i = blockIdx.x * blockDim.x + threadIdx.x;
    if (i < N_NODES) { g_cnt[i] = 1; g_off[i] = 0; }
}
__global__ void k_count(const int* __restrict__ col) {
    int e = blockIdx.x * blockDim.x + threadIdx.x;
    if (e < N_EDGES) atomicAdd(&g_cnt[col[e]], 1);
}
__global__ void k_scan1() {   // block inclusive scan + dinv
    __shared__ int s[1024];
    int i = blockIdx.x * 1024 + threadIdx.x;
    int v = (i < N_NODES) ? g_cnt[i] : 0;
    if (i < N_NODES) g_dinv[i] = rsqrtf((float)v);
    s[threadIdx.x] = v;
    __syncthreads();
    for (int d = 1; d < 1024; d <<= 1) {
        int t = (threadIdx.x >= d) ? s[threadIdx.x - d] : 0;
        __syncthreads();
        s[threadIdx.x] += t;
        __syncthreads();
    }
    if (i < N_NODES) g_incl[i] = s[threadIdx.x];
    if (threadIdx.x == 1023) g_aux[blockIdx.x] = s[1023];
}
__global__ void k_scanaux(int nb) {      // 128-wide exclusive scan
    __shared__ int s[128];
    int v = (threadIdx.x < nb) ? g_aux[threadIdx.x] : 0;
    s[threadIdx.x] = v;
    __syncthreads();
    for (int d = 1; d < 128; d <<= 1) {
        int t = (threadIdx.x >= d) ? s[threadIdx.x - d] : 0;
        __syncthreads();
        s[threadIdx.x] += t;
        __syncthreads();
    }
    if (threadIdx.x < nb) g_auxex[threadIdx.x] = s[threadIdx.x] - v;
}
__global__ void k_finalize() {
    int i = blockIdx.x * blockDim.x + threadIdx.x;
    if (i < N_NODES) {
        g_colptr[i + 1] = g_incl[i] + g_auxex[i >> 10];
        if (i == 0) g_colptr[0] = 0;
    }
}
__global__ void k_fill(const int* __restrict__ rowp, const int* __restrict__ colp) {
    int i = blockIdx.x * blockDim.x + threadIdx.x;
    if (i < N_TOT) {
        int r, c;
        if (i < N_EDGES) { r = rowp[i]; c = colp[i]; }
        else             { r = c = i - N_EDGES; }
        int idx = g_colptr[c] + atomicAdd(&g_off[c], 1);
        g_erow[idx] = r;
    }
}

// ---------------- GEMM1: g_t = relu(x @ W1 + b1) -> bf16 ----------------
// R7 loop structure (single buffer, no register prefetch); epilogue stages
// fragments through smem (2 halves), fuses b1+relu, stores bf16.
#define G1_AS_LD 40
#define G1_BS_LD 264
#define G1_AS_BYTES (64 * G1_AS_LD * 2)              // 5120
#define G1_BS_BYTES (32 * G1_BS_LD * 2)              // 16896
#define G1_CS_BYTES (64 * 132 * 4)                   // 33792 (aliases As+Bs)
#define G1_SMEM     G1_CS_BYTES                      // 33792 > 22016

__global__ __launch_bounds__(256) void k_gemm1(const float* __restrict__ A,
                                               const float* __restrict__ W1,
                                               const float* __restrict__ b1) {
    extern __shared__ char smraw[];
    __nv_bfloat16* As = (__nv_bfloat16*)smraw;                   // [64][40]
    __nv_bfloat16* Bs = (__nv_bfloat16*)(smraw + G1_AS_BYTES);   // [32][264]
    float* Cs = (float*)smraw;                                   // [64][132] (aliased, epilogue only)

    const int tid = threadIdx.x;
    const int warp = tid >> 5;
    const int wr = warp >> 2, wc = warp & 3;
    const int m0 = blockIdx.x * 64;

    wmma::fragment<wmma::accumulator, 16, 16, 16, float> c[2][4];
    #pragma unroll
    for (int i = 0; i < 2; i++)
        #pragma unroll
        for (int j = 0; j < 4; j++) wmma::fill_fragment(c[i][j], 0.f);

    const int ar = tid >> 2, ac8 = (tid & 3) << 3;   // A: 64 rows x 4 groups of 8
    const float* Arow = A + (size_t)min(m0 + ar, N_NODES - 1) * F_IN;

    for (int k0 = 0; k0 < F_IN; k0 += 32) {
        {   // A tile 64x32: 8 bf16 per thread
            float4 v0 = *(const float4*)&Arow[k0 + ac8];
            float4 v1 = *(const float4*)&Arow[k0 + ac8 + 4];
            *(uint4*)&As[ar * G1_AS_LD + ac8] = pack8_bf16(v0, v1);
        }
        #pragma unroll
        for (int l = 0; l < 4; l++) {   // B tile 32x256
            int idx = tid + l * 256;
            int br = idx >> 5, bc8 = (idx & 31) << 3;
            float4 v0 = *(const float4*)&W1[(size_t)(k0 + br) * F_MID + bc8];
            float4 v1 = *(const float4*)&W1[(size_t)(k0 + br) * F_MID + bc8 + 4];
            *(uint4*)&Bs[br * G1_BS_LD + bc8] = pack8_bf16(v0, v1);
        }
        __syncthreads();
        #pragma unroll
        for (int kk = 0; kk < 32; kk += 16) {
            wmma::fragment<wmma::matrix_a, 16, 16, 16, __nv_bfloat16, wmma::row_major> a0, a1;
            wmma::load_matrix_sync(a0, &As[(wr * 32) * G1_AS_LD + kk],      G1_AS_LD);
            wmma::load_matrix_sync(a1, &As[(wr * 32 + 16) * G1_AS_LD + kk], G1_AS_LD);
            #pragma unroll
            for (int j = 0; j < 4; j++) {
                wmma::fragment<wmma::matrix_b, 16, 16, 16, __nv_bfloat16, wmma::row_major> b;
                wmma::load_matrix_sync(b, &Bs[kk * G1_BS_LD + wc * 64 + j * 16], G1_BS_LD);
                wmma::mma_sync(c[0][j], a0, b, c[0][j]);
                wmma::mma_sync(c[1][j], a1, b, c[1][j]);
            }
        }
        __syncthreads();
    }

    // epilogue: two 128-col halves through Cs (aliases pipeline smem)
    #pragma unroll
    for (int half = 0; half < 2; half++) {
        if ((wc >> 1) == half) {
            int wcl = wc & 1;
            #pragma unroll
            for (int i = 0; i < 2; i++)
                #pragma unroll
                for (int j = 0; j < 4; j++)
                    wmma::store_matrix_sync(&Cs[(wr * 32 + i * 16) * 132 + wcl * 64 + j * 16],
                                            c[i][j], 132, wmma::mem_row_major);
        }
        __syncthreads();
        #pragma unroll
        for (int l = 0; l < 4; l++) {
            int idx = tid + l * 256;            // 1024 chunks of 8 floats (64 x 128)
            int r = idx >> 4, c8 = (idx & 15) << 3;
            float4 v0 = *(float4*)&Cs[r * 132 + c8];
            float4 v1 = *(float4*)&Cs[r * 132 + c8 + 4];
            float4 u0 = *(const float4*)&b1[half * 128 + c8];
            float4 u1 = *(const float4*)&b1[half * 128 + c8 + 4];
            v0.x = fmaxf(v0.x + u0.x, 0.f); v0.y = fmaxf(v0.y + u0.y, 0.f);
            v0.z = fmaxf(v0.z + u0.z, 0.f); v0.w = fmaxf(v0.w + u0.w, 0.f);
            v1.x = fmaxf(v1.x + u1.x, 0.f); v1.y = fmaxf(v1.y + u1.y, 0.f);
            v1.z = fmaxf(v1.z + u1.z, 0.f); v1.w = fmaxf(v1.w + u1.w, 0.f);
            *(uint4*)&g_t[(size_t)(m0 + r) * F_MID + half * 128 + c8] = pack8_bf16(v0, v1);
        }
        __syncthreads();
    }
}

// ---------------- GEMM2: h = t @ W2 + b2 (t already relu'd bf16) ----------------
#define A2_LD 40
#define B2_LD 80
__global__ __launch_bounds__(128) void k_gemm2(const float* __restrict__ B,
                                               const float* __restrict__ b2) {
    __shared__ __nv_bfloat16 As[64][A2_LD];
    __shared__ __nv_bfloat16 Bs[32][B2_LD];
    __shared__ float Cs[64][68];
    const int tid = threadIdx.x;
    const int warp = tid >> 5;
    const int wr = warp >> 1, wc = warp & 1;
    const int m0 = blockIdx.x * 64;

    wmma::fragment<wmma::accumulator, 16, 16, 16, float> c[2][2];
    #pragma unroll
    for (int i = 0; i < 2; i++)
        #pragma unroll
        for (int j = 0; j < 2; j++) wmma::fill_fragment(c[i][j], 0.f);

    for (int k0 = 0; k0 < F_MID; k0 += 32) {
        #pragma unroll
        for (int l = 0; l < 2; l++) {   // A tile 64x32 bf16: pure copy
            int idx = tid + l * 128;
            int r = idx >> 2, c8 = (idx & 3) << 3;
            *(uint4*)&As[r][c8] =
                *(const uint4*)&g_t[(size_t)(m0 + r) * F_MID + k0 + c8];
        }
        #pragma unroll
        for (int l = 0; l < 2; l++) {   // B tile 32x64
            int idx = tid + l * 128;
            int br = idx >> 3, bc8 = (idx & 7) << 3;
            float4 v0 = *(const float4*)&B[(size_t)(k0 + br) * F_OUT + bc8];
            float4 v1 = *(const float4*)&B[(size_t)(k0 + br) * F_OUT + bc8 + 4];
            *(uint4*)&Bs[br][bc8] = pack8_bf16(v0, v1);
        }
        __syncthreads();
        #pragma unroll
        for (int kk = 0; kk < 32; kk += 16) {
            wmma::fragment<wmma::matrix_a, 16, 16, 16, __nv_bfloat16, wmma::row_major> a0, a1;
            wmma::fragment<wmma::matrix_b, 16, 16, 16, __nv_bfloat16, wmma::row_major> b0, b1f;
            wmma::load_matrix_sync(a0, &As[wr * 32][kk],      A2_LD);
            wmma::load_matrix_sync(a1, &As[wr * 32 + 16][kk], A2_LD);
            wmma::load_matrix_sync(b0, &Bs[kk][wc * 32],      B2_LD);
            wmma::load_matrix_sync(b1f, &Bs[kk][wc * 32 + 16], B2_LD);
            wmma::mma_sync(c[0][0], a0, b0,  c[0][0]);
            wmma::mma_sync(c[0][1], a0, b1f, c[0][1]);
            wmma::mma_sync(c[1][0], a1, b0,  c[1][0]);
            wmma::mma_sync(c[1][1], a1, b1f, c[1][1]);
        }
        __syncthreads();
    }
    #pragma unroll
    for (int i = 0; i < 2; i++)
        #pragma unroll
        for (int j = 0; j < 2; j++)
            wmma::store_matrix_sync(&Cs[wr * 32 + i * 16][wc * 32 + j * 16],
                                    c[i][j], 68, wmma::mem_row_major);
    __syncthreads();
    #pragma unroll
    for (int l = 0; l < 8; l++) {
        int idx = tid + l * 128;
        int r = idx >> 4, c4 = (idx & 15) << 2;
        float4 v = *(float4*)&Cs[r][c4];
        float4 bb = *(const float4*)&b2[c4];
        v.x += bb.x; v.y += bb.y; v.z += bb.z; v.w += bb.w;
        int row = m0 + r;
        float di = (row < N_NODES) ? g_dinv[row] : 0.f;
        size_t oh = (size_t)row * 32 + (c4 >> 1);
        g_hh[oh]     = __floats2half2_rn(v.x, v.y);
        g_hh[oh + 1] = __floats2half2_rn(v.z, v.w);
        g_y0[oh]     = __floats2half2_rn(di * v.x, di * v.y);
        g_y0[oh + 1] = __floats2half2_rn(di * v.z, di * v.w);
    }
}

// ---------------- APPNP propagation ----------------
__device__ __forceinline__ void acc8(float2& a0, float2& a1, float2& a2, float2& a3,
                                     const __half2* __restrict__ zin, int r, int k) {
    float4 v = *(const float4*)&zin[(size_t)r * 32 + k * 4];
    const __half2* hp = (const __half2*)&v;
    float2 t0 = __half22float2(hp[0]);
    float2 t1 = __half22float2(hp[1]);
    float2 t2 = __half22float2(hp[2]);
    float2 t3 = __half22float2(hp[3]);
    a0.x += t0.x; a0.y += t0.y;
    a1.x += t1.x; a1.y += t1.y;
    a2.x += t2.x; a2.y += t2.y;
    a3.x += t3.x; a3.y += t3.y;
}

__global__ void k_prop(float* __restrict__ outF, int it) {
    const __half2* __restrict__ zin = (it & 1) ? g_y1 : g_y0;
    __half2* __restrict__ zout = (it & 1) ? g_y0 : g_y1;
    const int warp = threadIdx.x >> 5, lane = threadIdx.x & 31;
    const int node = blockIdx.x * 8 + warp;
    if (node >= N_NODES) return;
    const int g = lane >> 3, k = lane & 7;
    const int s = g_colptr[node], e = g_colptr[node + 1];

    float2 a0 = {0.f, 0.f}, a1 = {0.f, 0.f}, a2 = {0.f, 0.f}, a3 = {0.f, 0.f};
    int i = s + g;
    while (i + 12 < e) {                 // four independent 512B gathers in flight
        int r0 = g_erow[i];
        int r1 = g_erow[i + 4];
        int r2 = g_erow[i + 8];
        int r3 = g_erow[i + 12];
        acc8(a0, a1, a2, a3, zin, r0, k);
        acc8(a0, a1, a2, a3, zin, r1, k);
        acc8(a0, a1, a2, a3, zin, r2, k);
        acc8(a0, a1, a2, a3, zin, r3, k);
        i += 16;
    }
    while (i < e) {
        acc8(a0, a1, a2, a3, zin, g_erow[i], k);
        i += 4;
    }
    #pragma unroll
    for (int d = 8; d <= 16; d <<= 1) {
        a0.x += __shfl_xor_sync(0xffffffffu, a0.x, d);
        a0.y += __shfl_xor_sync(0xffffffffu, a0.y, d);
        a1.x += __shfl_xor_sync(0xffffffffu, a1.x, d);
        a1.y += __shfl_xor_sync(0xffffffffu, a1.y, d);
        a2.x += __shfl_xor_sync(0xffffffffu, a2.x, d);
        a2.y += __shfl_xor_sync(0xffffffffu, a2.y, d);
        a3.x += __shfl_xor_sync(0xffffffffu, a3.x, d);
        a3.y += __shfl_xor_sync(0xffffffffu, a3.y, d);
    }
    const float dc = g_dinv[node];
    float4 hv = *(const float4*)&g_hh[(size_t)node * 32 + k * 4];
    const __half2* hp = (const __half2*)&hv;
    float2 h0 = __half22float2(hp[0]), h1 = __half22float2(hp[1]);
    float2 h2 = __half22float2(hp[2]), h3 = __half22float2(hp[3]);
    const float w = 0.9f * dc;
    float z0x = w * a0.x + 0.1f * h0.x, z0y = w * a0.y + 0.1f * h0.y;
    float z1x = w * a1.x + 0.1f * h1.x, z1y = w * a1.y + 0.1f * h1.y;
    float z2x = w * a2.x + 0.1f * h2.x, z2y = w * a2.y + 0.1f * h2.y;
    float z3x = w * a3.x + 0.1f * h3.x, z3y = w * a3.y + 0.1f * h3.y;

    if (it != K_STEPS - 1) {
        if (g == 0) {
            __half2 o0 = __floats2half2_rn(dc * z0x, dc * z0y);
            __half2 o1 = __floats2half2_rn(dc * z1x, dc * z1y);
            __half2 o2 = __floats2half2_rn(dc * z2x, dc * z2y);
            __half2 o3 = __floats2half2_rn(dc * z3x, dc * z3y);
            uint4 pk;
            pk.x = *(unsigned*)&o0; pk.y = *(unsigned*)&o1;
            pk.z = *(unsigned*)&o2; pk.w = *(unsigned*)&o3;
            *(uint4*)&zout[(size_t)node * 32 + k * 4] = pk;
        }
    } else {
        float m = fmaxf(fmaxf(fmaxf(z0x, z0y), fmaxf(z1x, z1y)),
                        fmaxf(fmaxf(z2x, z2y), fmaxf(z3x, z3y)));
        #pragma unroll
        for (int d = 1; d <= 4; d <<= 1) m = fmaxf(m, __shfl_xor_sync(0xffffffffu, m, d));
        float sm = __expf(z0x - m) + __expf(z0y - m) + __expf(z1x - m) + __expf(z1y - m)
                 + __expf(z2x - m) + __expf(z2y - m) + __expf(z3x - m) + __expf(z3y - m);
        #pragma unroll
        for (int d = 1; d <= 4; d <<= 1) sm += __shfl_xor_sync(0xffffffffu, sm, d);
        float l = m + __logf(sm);
        if (g == 0) {
            float4 o;
            o.x = z0x - l; o.y = z0y - l; o.z = z1x - l; o.w = z1y - l;
            *(float4*)&outF[(size_t)node * F_OUT + k * 8] = o;
            o.x = z2x - l; o.y = z2y - l; o.z = z3x - l; o.w = z3y - l;
            *(float4*)&outF[(size_t)node * F_OUT + k * 8 + 4] = o;
        }
    }
}

// ---------------- launch ----------------
extern "C" void kernel_launch(void* const* d_in, const int* in_sizes, int n_in,
                              void* d_out, int out_size) {
    const float* x  = (const float*)d_in[0];
    const int*   ei = (const int*)d_in[1];
    const float* W1 = (const float*)d_in[2];
    const float* b1 = (const float*)d_in[3];
    const float* W2 = (const float*)d_in[4];
    const float* b2 = (const float*)d_in[5];
    float* out = (float*)d_out;

    const int* rowp = ei;
    const int* colp = ei + N_EDGES;

    // CSR-by-destination build
    k_init<<<(N_NODES + 255) / 256, 256>>>();
    k_count<<<(N_EDGES + 255) / 256, 256>>>(colp);
    int nb = (N_NODES + 1023) / 1024;
    k_scan1<<<nb, 1024>>>();
    k_scanaux<<<1, 128>>>(nb);
    k_finalize<<<(N_NODES + 255) / 256, 256>>>();
    k_fill<<<(N_TOT + 255) / 256, 256>>>(rowp, colp);

    // MLP (bf16 tensor cores, fp32 accumulate)
    int mb = (N_NODES + 63) / 64;     // 1563
    k_gemm1<<<mb, 256, G1_SMEM>>>(x, W1, b1);
    k_gemm2<<<mb, 128>>>(W2, b2);

    // K propagation steps
    for (int it = 0; it < K_STEPS; ++it)
        k_prop<<<(N_NODES + 7) / 8, 256>>>(out, it);
}